// round 2
// baseline (speedup 1.0000x reference)
#include <cuda_runtime.h>
#include <math.h>

#define S_LEN   2048
#define HIDDEN  4096
#define NH      32
#define HD      128
#define QKV_DIM 6144      // (32 + 8 + 8) * 128
#define K_OFF   4096      // start of K region in a qkv row
#define V_OFF   5120      // start of V region in a qkv row

// Scratch (allocation-free rule: __device__ globals)
__device__ float g_qkv[S_LEN * QKV_DIM];      // ~50 MB
__device__ float g_attn[S_LEN * NH * HD];     // ~33 MB

// ---------------------------------------------------------------------------
// SGEMM NT: C[M,N] = A[M,K] * B[N,K]^T   (both inputs K-major row-major)
// 64x64 tile, BK=16, 256 threads, 4x4 microtile.
// ---------------------------------------------------------------------------
#define GBM 64
#define GBN 64
#define GBK 16
#define GPAD 68   // row stride in floats: keeps float4 reads 16B-aligned, 2-way STS conflicts only

__global__ void __launch_bounds__(256) sgemm_nt(const float* __restrict__ A,
                                                const float* __restrict__ B,
                                                float* __restrict__ C,
                                                int M, int N, int K) {
    __shared__ float As[GBK * GPAD];
    __shared__ float Bs[GBK * GPAD];
    const int tid = threadIdx.x;
    const int tx = tid & 15, ty = tid >> 4;
    const int row0 = blockIdx.y * GBM, col0 = blockIdx.x * GBN;
    const int lr = tid >> 2;            // 0..63 : tile row loaded by this thread
    const int lk = (tid & 3) << 2;      // 0,4,8,12 : k offset
    const float* Ap = A + (size_t)(row0 + lr) * K + lk;
    const float* Bp = B + (size_t)(col0 + lr) * K + lk;

    float acc[4][4] = {};
    for (int k0 = 0; k0 < K; k0 += GBK) {
        float4 a4 = *(const float4*)(Ap + k0);
        float4 b4 = *(const float4*)(Bp + k0);
        As[(lk+0)*GPAD+lr]=a4.x; As[(lk+1)*GPAD+lr]=a4.y;
        As[(lk+2)*GPAD+lr]=a4.z; As[(lk+3)*GPAD+lr]=a4.w;
        Bs[(lk+0)*GPAD+lr]=b4.x; Bs[(lk+1)*GPAD+lr]=b4.y;
        Bs[(lk+2)*GPAD+lr]=b4.z; Bs[(lk+3)*GPAD+lr]=b4.w;
        __syncthreads();
        #pragma unroll
        for (int kk = 0; kk < GBK; kk++) {
            float4 av = *(const float4*)(As + kk*GPAD + (ty<<2));
            float4 bv = *(const float4*)(Bs + kk*GPAD + (tx<<2));
            float a[4] = {av.x, av.y, av.z, av.w};
            float b[4] = {bv.x, bv.y, bv.z, bv.w};
            #pragma unroll
            for (int i = 0; i < 4; i++)
                #pragma unroll
                for (int j = 0; j < 4; j++)
                    acc[i][j] = fmaf(a[i], b[j], acc[i][j]);
        }
        __syncthreads();
    }
    #pragma unroll
    for (int i = 0; i < 4; i++) {
        float4 o = make_float4(acc[i][0], acc[i][1], acc[i][2], acc[i][3]);
        *(float4*)(C + (size_t)(row0 + ty*4 + i) * N + col0 + (tx<<2)) = o;
    }
}

// ---------------------------------------------------------------------------
// RoPE: in-place on the first 40 "heads" of each qkv row (32 Q + 8 K).
// Q region starts at 0, K region at 4096 = 32*128, so head h -> offset h*128.
// ---------------------------------------------------------------------------
__global__ void rope_kernel() {
    int idx = blockIdx.x * blockDim.x + threadIdx.x;
    if (idx >= S_LEN * 40 * 64) return;
    int d = idx & 63;
    int h = (idx >> 6) % 40;
    int s = idx / (64 * 40);
    // freq = 10000^(-d/64) = 2^(-d * log2(10000)/64)
    float freq = exp2f(-0.20762050593046013f * (float)d);
    float ang = (float)s * freq;
    float sn, cs;
    sincosf(ang, &sn, &cs);
    float* base = g_qkv + (size_t)s * QKV_DIM + h * HD;
    float x1 = base[d];
    float x2 = base[d + 64];
    base[d]      = x1 * cs - x2 * sn;
    base[d + 64] = x1 * sn + x2 * cs;
}

// ---------------------------------------------------------------------------
// Flash attention: 64 queries x 64 keys per tile, online softmax, GQA (kvh=h/4).
// Q/K staged transposed+swizzled in smem ([d][m], 16-float4-group XOR swizzle)
// so the 64x64x128 score GEMM runs on conflict-free LDS.128.
// ---------------------------------------------------------------------------
#define ABM 64
#define ABN 64
// smem layout (floats)
#define SM_QT 0
#define SM_KT (SM_QT + 128*64)
#define SM_VS (SM_KT + 128*64)
#define SM_SC (SM_VS + 64*128)
#define SM_RS (SM_SC + 64*64)
#define SM_RL (SM_RS + 64)
#define SM_TOTAL (SM_RL + 64)          // 28800 floats = 115200 bytes

__device__ __forceinline__ int sw_idx(int d, int n) {
    // transposed [128][64] tile, swizzle column group by (d>>2)
    return d * 64 + (((((n >> 2) ^ ((d >> 2) & 15))) << 2) | (n & 3));
}

__global__ void __launch_bounds__(256, 2) attn_kernel() {
    extern __shared__ float sm[];
    float* Qt = sm + SM_QT;
    float* Kt = sm + SM_KT;
    float* Vs = sm + SM_VS;
    float* Sc = sm + SM_SC;
    float* row_scale = sm + SM_RS;
    float* row_l = sm + SM_RL;

    const int tid = threadIdx.x;
    const int mb = gridDim.x - 1 - blockIdx.x;   // heaviest blocks first
    const int h = blockIdx.y;
    const int kvh = h >> 2;
    const int q0 = mb * ABM;
    const float scale = 0.08838834764831845f;    // 1/sqrt(128)

    const int tx = tid & 15, ty = tid >> 4;      // phase1: 4x4 microtile, phase3: rows ty*4, dims tx*8
    const int r = tid >> 2, qq = tid & 3;        // phase2: 4 threads per score row

    // Load Q tile (transposed + swizzled, pre-scaled)
    {
        const float* Qg = g_qkv + (size_t)q0 * QKV_DIM + h * HD;
        for (int e = tid; e < ABM * HD / 4; e += 256) {
            int m = e >> 5;
            int d = (e & 31) << 2;
            float4 v = *(const float4*)(Qg + (size_t)m * QKV_DIM + d);
            Qt[sw_idx(d+0, m)] = v.x * scale;
            Qt[sw_idx(d+1, m)] = v.y * scale;
            Qt[sw_idx(d+2, m)] = v.z * scale;
            Qt[sw_idx(d+3, m)] = v.w * scale;
        }
    }

    float m_old = -INFINITY, l_run = 0.0f;       // valid per quad-role (row r)
    float acc[4][8] = {};
    const int nblocks = mb + 1;

    for (int kb = 0; kb < nblocks; kb++) {
        const int n0 = kb * ABN;
        // ---- load K (transposed+swizzled) and V (row-major) tiles ----
        {
            const float* Kg = g_qkv + (size_t)n0 * QKV_DIM + K_OFF + kvh * HD;
            const float* Vg = g_qkv + (size_t)n0 * QKV_DIM + V_OFF + kvh * HD;
            for (int e = tid; e < ABN * HD / 4; e += 256) {
                int n = e >> 5;
                int d = (e & 31) << 2;
                float4 kv = *(const float4*)(Kg + (size_t)n * QKV_DIM + d);
                Kt[sw_idx(d+0, n)] = kv.x;
                Kt[sw_idx(d+1, n)] = kv.y;
                Kt[sw_idx(d+2, n)] = kv.z;
                Kt[sw_idx(d+3, n)] = kv.w;
                float4 vv = *(const float4*)(Vg + (size_t)n * QKV_DIM + d);
                *(float4*)(Vs + n * 128 + d) = vv;
            }
        }
        __syncthreads();

        // ---- phase 1: S = Q K^T (64x64x128) ----
        {
            float s4[4][4] = {};
            #pragma unroll 4
            for (int k = 0; k < 128; k++) {
                int sw = (k >> 2) & 15;
                float4 av = *(const float4*)(Qt + k*64 + ((ty ^ sw) << 2));
                float4 bv = *(const float4*)(Kt + k*64 + ((tx ^ sw) << 2));
                float a[4] = {av.x, av.y, av.z, av.w};
                float b[4] = {bv.x, bv.y, bv.z, bv.w};
                #pragma unroll
                for (int i = 0; i < 4; i++)
                    #pragma unroll
                    for (int j = 0; j < 4; j++)
                        s4[i][j] = fmaf(a[i], b[j], s4[i][j]);
            }
            #pragma unroll
            for (int i = 0; i < 4; i++) {
                float4 o = make_float4(s4[i][0], s4[i][1], s4[i][2], s4[i][3]);
                *(float4*)(Sc + (ty*4 + i) * 64 + (tx << 2)) = o;
            }
        }
        __syncthreads();

        // ---- phase 2: online softmax on row r (4 threads per row) ----
        {
            const bool diag = (kb == mb);
            const int cbase = qq * 16;
            float sc[16];
            #pragma unroll
            for (int j = 0; j < 16; j++) sc[j] = Sc[r * 64 + cbase + j];
            if (diag) {
                #pragma unroll
                for (int j = 0; j < 16; j++)
                    if (cbase + j > r) sc[j] = -INFINITY;
            }
            float ml = sc[0];
            #pragma unroll
            for (int j = 1; j < 16; j++) ml = fmaxf(ml, sc[j]);
            ml = fmaxf(ml, __shfl_xor_sync(0xffffffffu, ml, 1));
            ml = fmaxf(ml, __shfl_xor_sync(0xffffffffu, ml, 2));
            float m_new = fmaxf(m_old, ml);
            float rescale = __expf(m_old - m_new);
            float psum = 0.0f;
            #pragma unroll
            for (int j = 0; j < 16; j++) {
                float p = __expf(sc[j] - m_new);
                psum += p;
                Sc[r * 64 + cbase + j] = p;
            }
            psum += __shfl_xor_sync(0xffffffffu, psum, 1);
            psum += __shfl_xor_sync(0xffffffffu, psum, 2);
            l_run = l_run * rescale + psum;
            m_old = m_new;
            if (qq == 0) row_scale[r] = rescale;
        }
        __syncthreads();

        // ---- phase 3: O = O*diag(rescale) + P V  (64x128x64) ----
        {
            float fac[4];
            #pragma unroll
            for (int i = 0; i < 4; i++) fac[i] = row_scale[ty*4 + i];
            #pragma unroll
            for (int i = 0; i < 4; i++)
                #pragma unroll
                for (int j = 0; j < 8; j++) acc[i][j] *= fac[i];
            #pragma unroll 4
            for (int k = 0; k < 64; k++) {
                float4 v0 = *(const float4*)(Vs + k*128 + (tx << 3));
                float4 v1 = *(const float4*)(Vs + k*128 + (tx << 3) + 4);
                float p0 = Sc[(ty*4 + 0) * 64 + k];
                float p1 = Sc[(ty*4 + 1) * 64 + k];
                float p2 = Sc[(ty*4 + 2) * 64 + k];
                float p3 = Sc[(ty*4 + 3) * 64 + k];
                float v[8] = {v0.x, v0.y, v0.z, v0.w, v1.x, v1.y, v1.z, v1.w};
                float p[4] = {p0, p1, p2, p3};
                #pragma unroll
                for (int i = 0; i < 4; i++)
                    #pragma unroll
                    for (int j = 0; j < 8; j++)
                        acc[i][j] = fmaf(p[i], v[j], acc[i][j]);
            }
        }
        __syncthreads();   // protect K/V/Sc before next iteration's loads
    }

    // final normalization + writeout
    if (qq == 0) row_l[r] = l_run;
    __syncthreads();
    #pragma unroll
    for (int i = 0; i < 4; i++) {
        float inv = 1.0f / row_l[ty*4 + i];
        float4 o0 = make_float4(acc[i][0]*inv, acc[i][1]*inv, acc[i][2]*inv, acc[i][3]*inv);
        float4 o1 = make_float4(acc[i][4]*inv, acc[i][5]*inv, acc[i][6]*inv, acc[i][7]*inv);
        float* dst = g_attn + (size_t)(q0 + ty*4 + i) * (NH * HD) + h * HD + (tx << 3);
        *(float4*)(dst)     = o0;
        *(float4*)(dst + 4) = o1;
    }
}

// ---------------------------------------------------------------------------
extern "C" void kernel_launch(void* const* d_in, const int* in_sizes, int n_in,
                              void* d_out, int out_size) {
    const float* hidden = (const float*)d_in[0];
    const float* w_qkv  = (const float*)d_in[1];
    const float* w_o    = (const float*)d_in[2];
    float* out = (float*)d_out;

    float *qkv = nullptr, *attn = nullptr;
    cudaGetSymbolAddress((void**)&qkv,  g_qkv);
    cudaGetSymbolAddress((void**)&attn, g_attn);

    cudaFuncSetAttribute(attn_kernel, cudaFuncAttributeMaxDynamicSharedMemorySize,
                         SM_TOTAL * (int)sizeof(float));

    // 1) QKV projection: [2048,6144] = hidden [2048,4096] @ w_qkv^T
    dim3 g1(QKV_DIM / GBN, S_LEN / GBM);
    sgemm_nt<<<g1, 256>>>(hidden, w_qkv, qkv, S_LEN, QKV_DIM, HIDDEN);

    // 2) RoPE on Q and K regions (40 heads x 64 pairs per token)
    rope_kernel<<<(S_LEN * 40 * 64 + 255) / 256, 256>>>();

    // 3) Causal GQA flash attention -> g_attn [2048, 4096]
    attn_kernel<<<dim3(S_LEN / ABM, NH), 256, SM_TOTAL * (int)sizeof(float)>>>();

    // 4) Output projection: out [2048,4096] = g_attn @ w_o^T
    dim3 g2(HIDDEN / GBN, S_LEN / GBM);
    sgemm_nt<<<g2, 256>>>(attn, w_o, out, S_LEN, HIDDEN, HIDDEN);
}

// round 4
// speedup vs baseline: 2.4050x; 2.4050x over previous
#include <cuda_runtime.h>
#include <cstdint>
#include <math.h>

#define S_LEN   2048
#define HIDDEN  4096
#define NH      32
#define HD      128
#define QKV_DIM 6144      // (32 + 8 + 8) * 128
#define K_OFF   4096      // start of K region in a qkv row
#define V_OFF   5120      // start of V region in a qkv row

// Scratch (allocation-free rule: __device__ globals)
__device__ float g_qkv[S_LEN * QKV_DIM];      // ~50 MB
__device__ float g_attn[S_LEN * NH * HD];     // ~33 MB

__device__ __forceinline__ uint32_t smem_to_u32(const void* smem_ptr) {
    uint32_t addr;
    asm("{ .reg .u64 tmp; cvta.to.shared.u64 tmp, %1; cvt.u32.u64 %0, tmp; }"
        : "=r"(addr) : "l"(smem_ptr));
    return addr;
}

#define LDSM_X4(r0, r1, r2, r3, addr) \
    asm volatile("ldmatrix.sync.aligned.m8n8.x4.shared.b16 {%0,%1,%2,%3}, [%4];" \
                 : "=r"(r0), "=r"(r1), "=r"(r2), "=r"(r3) : "r"(addr))

#define CVT_TF32(x) \
    asm("cvt.rna.tf32.f32 %0, %1;" : "=r"(x) : "f"(__uint_as_float(x)))

#define MMA_TF32(d, a0, a1, a2, a3, b0, b1) \
    asm volatile("mma.sync.aligned.m16n8k8.row.col.f32.tf32.tf32.f32 " \
                 "{%0,%1,%2,%3}, {%4,%5,%6,%7}, {%8,%9}, {%0,%1,%2,%3};" \
                 : "+f"((d)[0]), "+f"((d)[1]), "+f"((d)[2]), "+f"((d)[3]) \
                 : "r"(a0), "r"(a1), "r"(a2), "r"(a3), "r"(b0), "r"(b1))

// ===========================================================================
// tf32 mma.sync GEMM NT: C[M,N] = A[M,K] * B[N,K]^T, fp32 in/out.
// 128x128 CTA tile, BK=32 floats (128B rows, XOR-8 swizzle), 2-stage cp.async
// double buffer, 8 warps in a 2(M)x4(N) grid, 64x32 warp tile.
// grid.x = M/128 (fast), grid.y = N/128.
// ===========================================================================
#define TBM 128
#define TBN 128
#define TBK 32
#define TILE_BYTES (TBM * TBK * 4)     // 16384
#define BUF_STRIDE (2 * TILE_BYTES)    // A+B per stage
#define GEMM_SMEM_TOTAL (2 * BUF_STRIDE)   // 65536

__global__ void __launch_bounds__(256) tmma_gemm_nt(const float* __restrict__ A,
                                                    const float* __restrict__ B,
                                                    float* __restrict__ C,
                                                    int N, int K) {
    extern __shared__ char smem[];
    const uint32_t sbase = smem_to_u32(smem);
    const int tid = threadIdx.x;
    const int lane = tid & 31;
    const int wid = tid >> 5;
    const int warp_m = wid & 1;        // 0..1 -> 64 rows each
    const int warp_n = wid >> 1;       // 0..3 -> 32 cols each
    const int row0 = blockIdx.x * TBM;
    const int col0 = blockIdx.y * TBN;

    // ldmatrix per-lane source mapping (see theory):
    const int seg = lane >> 3, r8 = lane & 7;
    const int a_row_off = ((seg & 1) << 3) + r8;   // + mf*16
    const int a_kh = seg >> 1;                      // 0/1 -> +4 cols
    const int b_row_off = ((seg >> 1) << 3) + r8;   // + nf2*16
    const int b_kh = seg & 1;

    float acc[4][4][4] = {};            // [mf][nf][c0..c3]

    const int NCHUNK = K / TBK;

    auto load_chunk = [&](int c, int buf) {
        const uint32_t sA = sbase + (uint32_t)buf * BUF_STRIDE;
        const uint32_t sB = sA + TILE_BYTES;
        const int k0 = c * TBK;
        #pragma unroll
        for (int i = 0; i < 4; i++) {
            int e = tid + i * 256;               // 0..1023
            int rr = e >> 3, cj = e & 7;
            uint32_t so = (uint32_t)rr * 128u + (uint32_t)((cj ^ (rr & 7)) << 4);
            const float* gA = A + (size_t)(row0 + rr) * K + k0 + cj * 4;
            const float* gB = B + (size_t)(col0 + rr) * K + k0 + cj * 4;
            asm volatile("cp.async.cg.shared.global [%0], [%1], 16;\n"
                         :: "r"(sA + so), "l"(gA) : "memory");
            asm volatile("cp.async.cg.shared.global [%0], [%1], 16;\n"
                         :: "r"(sB + so), "l"(gB) : "memory");
        }
        asm volatile("cp.async.commit_group;\n" ::: "memory");
    };

    load_chunk(0, 0);
    for (int c = 0; c < NCHUNK; c++) {
        if (c + 1 < NCHUNK) {
            load_chunk(c + 1, (c + 1) & 1);
            asm volatile("cp.async.wait_group 1;\n" ::: "memory");
        } else {
            asm volatile("cp.async.wait_group 0;\n" ::: "memory");
        }
        __syncthreads();

        const uint32_t sA = sbase + (uint32_t)(c & 1) * BUF_STRIDE;
        const uint32_t sB = sA + TILE_BYTES;
        #pragma unroll
        for (int ks = 0; ks < 4; ks++) {
            uint32_t a[4][4], b[2][4];
            #pragma unroll
            for (int mf = 0; mf < 4; mf++) {
                int row = warp_m * 64 + mf * 16 + a_row_off;
                uint32_t g = (uint32_t)((ks * 2 + a_kh) ^ (row & 7));
                uint32_t addr = sA + (uint32_t)row * 128u + g * 16u;
                LDSM_X4(a[mf][0], a[mf][1], a[mf][2], a[mf][3], addr);
            }
            #pragma unroll
            for (int nf2 = 0; nf2 < 2; nf2++) {
                int row = warp_n * 32 + nf2 * 16 + b_row_off;
                uint32_t g = (uint32_t)((ks * 2 + b_kh) ^ (row & 7));
                uint32_t addr = sB + (uint32_t)row * 128u + g * 16u;
                LDSM_X4(b[nf2][0], b[nf2][1], b[nf2][2], b[nf2][3], addr);
            }
            #pragma unroll
            for (int mf = 0; mf < 4; mf++)
                #pragma unroll
                for (int i = 0; i < 4; i++) CVT_TF32(a[mf][i]);
            #pragma unroll
            for (int nf2 = 0; nf2 < 2; nf2++)
                #pragma unroll
                for (int i = 0; i < 4; i++) CVT_TF32(b[nf2][i]);
            #pragma unroll
            for (int mf = 0; mf < 4; mf++)
                #pragma unroll
                for (int nf = 0; nf < 4; nf++) {
                    uint32_t bb0 = b[nf >> 1][(nf & 1) * 2 + 0];
                    uint32_t bb1 = b[nf >> 1][(nf & 1) * 2 + 1];
                    MMA_TF32(acc[mf][nf], a[mf][0], a[mf][1], a[mf][2], a[mf][3],
                             bb0, bb1);
                }
        }
        __syncthreads();
    }

    // Epilogue: c0,c1 at (row, col..col+1); c2,c3 at (row+8, col..col+1)
    #pragma unroll
    for (int mf = 0; mf < 4; mf++) {
        int grow = row0 + warp_m * 64 + mf * 16 + (lane >> 2);
        #pragma unroll
        for (int nf = 0; nf < 4; nf++) {
            int gcol = col0 + warp_n * 32 + nf * 8 + ((lane & 3) << 1);
            *(float2*)(C + (size_t)grow * N + gcol) =
                make_float2(acc[mf][nf][0], acc[mf][nf][1]);
            *(float2*)(C + (size_t)(grow + 8) * N + gcol) =
                make_float2(acc[mf][nf][2], acc[mf][nf][3]);
        }
    }
}

// ---------------------------------------------------------------------------
// RoPE: in-place on the first 40 "heads" of each qkv row (32 Q + 8 K).
// ---------------------------------------------------------------------------
__global__ void rope_kernel() {
    int idx = blockIdx.x * blockDim.x + threadIdx.x;
    if (idx >= S_LEN * 40 * 64) return;
    int d = idx & 63;
    int h = (idx >> 6) % 40;
    int s = idx / (64 * 40);
    float freq = exp2f(-0.20762050593046013f * (float)d);
    float ang = (float)s * freq;
    float sn, cs;
    sincosf(ang, &sn, &cs);
    float* base = g_qkv + (size_t)s * QKV_DIM + h * HD;
    float x1 = base[d];
    float x2 = base[d + 64];
    base[d]      = x1 * cs - x2 * sn;
    base[d + 64] = x1 * sn + x2 * cs;
}

// ---------------------------------------------------------------------------
// Flash attention: 64 queries x 64 keys per tile, online softmax, GQA (kvh=h/4).
// (unchanged; tensor-core port is next round's target)
// ---------------------------------------------------------------------------
#define ABM 64
#define ABN 64
#define SM_QT 0
#define SM_KT (SM_QT + 128*64)
#define SM_VS (SM_KT + 128*64)
#define SM_SC (SM_VS + 64*128)
#define SM_RS (SM_SC + 64*64)
#define SM_RL (SM_RS + 64)
#define SM_TOTAL (SM_RL + 64)          // 28800 floats = 115200 bytes

__device__ __forceinline__ int sw_idx(int d, int n) {
    return d * 64 + (((((n >> 2) ^ ((d >> 2) & 15))) << 2) | (n & 3));
}

__global__ void __launch_bounds__(256, 2) attn_kernel() {
    extern __shared__ float sm[];
    float* Qt = sm + SM_QT;
    float* Kt = sm + SM_KT;
    float* Vs = sm + SM_VS;
    float* Sc = sm + SM_SC;
    float* row_scale = sm + SM_RS;
    float* row_l = sm + SM_RL;

    const int tid = threadIdx.x;
    const int mb = gridDim.x - 1 - blockIdx.x;   // heaviest blocks first
    const int h = blockIdx.y;
    const int kvh = h >> 2;
    const int q0 = mb * ABM;
    const float scale = 0.08838834764831845f;    // 1/sqrt(128)

    const int tx = tid & 15, ty = tid >> 4;
    const int r = tid >> 2, qq = tid & 3;

    {
        const float* Qg = g_qkv + (size_t)q0 * QKV_DIM + h * HD;
        for (int e = tid; e < ABM * HD / 4; e += 256) {
            int m = e >> 5;
            int d = (e & 31) << 2;
            float4 v = *(const float4*)(Qg + (size_t)m * QKV_DIM + d);
            Qt[sw_idx(d+0, m)] = v.x * scale;
            Qt[sw_idx(d+1, m)] = v.y * scale;
            Qt[sw_idx(d+2, m)] = v.z * scale;
            Qt[sw_idx(d+3, m)] = v.w * scale;
        }
    }

    float m_old = -INFINITY, l_run = 0.0f;
    float acc[4][8] = {};
    const int nblocks = mb + 1;

    for (int kb = 0; kb < nblocks; kb++) {
        const int n0 = kb * ABN;
        {
            const float* Kg = g_qkv + (size_t)n0 * QKV_DIM + K_OFF + kvh * HD;
            const float* Vg = g_qkv + (size_t)n0 * QKV_DIM + V_OFF + kvh * HD;
            for (int e = tid; e < ABN * HD / 4; e += 256) {
                int n = e >> 5;
                int d = (e & 31) << 2;
                float4 kv = *(const float4*)(Kg + (size_t)n * QKV_DIM + d);
                Kt[sw_idx(d+0, n)] = kv.x;
                Kt[sw_idx(d+1, n)] = kv.y;
                Kt[sw_idx(d+2, n)] = kv.z;
                Kt[sw_idx(d+3, n)] = kv.w;
                float4 vv = *(const float4*)(Vg + (size_t)n * QKV_DIM + d);
                *(float4*)(Vs + n * 128 + d) = vv;
            }
        }
        __syncthreads();

        {
            float s4[4][4] = {};
            #pragma unroll 4
            for (int k = 0; k < 128; k++) {
                int sw = (k >> 2) & 15;
                float4 av = *(const float4*)(Qt + k*64 + ((ty ^ sw) << 2));
                float4 bv = *(const float4*)(Kt + k*64 + ((tx ^ sw) << 2));
                float a[4] = {av.x, av.y, av.z, av.w};
                float b[4] = {bv.x, bv.y, bv.z, bv.w};
                #pragma unroll
                for (int i = 0; i < 4; i++)
                    #pragma unroll
                    for (int j = 0; j < 4; j++)
                        s4[i][j] = fmaf(a[i], b[j], s4[i][j]);
            }
            #pragma unroll
            for (int i = 0; i < 4; i++) {
                float4 o = make_float4(s4[i][0], s4[i][1], s4[i][2], s4[i][3]);
                *(float4*)(Sc + (ty*4 + i) * 64 + (tx << 2)) = o;
            }
        }
        __syncthreads();

        {
            const bool diag = (kb == mb);
            const int cbase = qq * 16;
            float sc[16];
            #pragma unroll
            for (int j = 0; j < 16; j++) sc[j] = Sc[r * 64 + cbase + j];
            if (diag) {
                #pragma unroll
                for (int j = 0; j < 16; j++)
                    if (cbase + j > r) sc[j] = -INFINITY;
            }
            float ml = sc[0];
            #pragma unroll
            for (int j = 1; j < 16; j++) ml = fmaxf(ml, sc[j]);
            ml = fmaxf(ml, __shfl_xor_sync(0xffffffffu, ml, 1));
            ml = fmaxf(ml, __shfl_xor_sync(0xffffffffu, ml, 2));
            float m_new = fmaxf(m_old, ml);
            float rescale = __expf(m_old - m_new);
            float psum = 0.0f;
            #pragma unroll
            for (int j = 0; j < 16; j++) {
                float p = __expf(sc[j] - m_new);
                psum += p;
                Sc[r * 64 + cbase + j] = p;
            }
            psum += __shfl_xor_sync(0xffffffffu, psum, 1);
            psum += __shfl_xor_sync(0xffffffffu, psum, 2);
            l_run = l_run * rescale + psum;
            m_old = m_new;
            if (qq == 0) row_scale[r] = rescale;
        }
        __syncthreads();

        {
            float fac[4];
            #pragma unroll
            for (int i = 0; i < 4; i++) fac[i] = row_scale[ty*4 + i];
            #pragma unroll
            for (int i = 0; i < 4; i++)
                #pragma unroll
                for (int j = 0; j < 8; j++) acc[i][j] *= fac[i];
            #pragma unroll 4
            for (int k = 0; k < 64; k++) {
                float4 v0 = *(const float4*)(Vs + k*128 + (tx << 3));
                float4 v1 = *(const float4*)(Vs + k*128 + (tx << 3) + 4);
                float p0 = Sc[(ty*4 + 0) * 64 + k];
                float p1 = Sc[(ty*4 + 1) * 64 + k];
                float p2 = Sc[(ty*4 + 2) * 64 + k];
                float p3 = Sc[(ty*4 + 3) * 64 + k];
                float v[8] = {v0.x, v0.y, v0.z, v0.w, v1.x, v1.y, v1.z, v1.w};
                float p[4] = {p0, p1, p2, p3};
                #pragma unroll
                for (int i = 0; i < 4; i++)
                    #pragma unroll
                    for (int j = 0; j < 8; j++)
                        acc[i][j] = fmaf(p[i], v[j], acc[i][j]);
            }
        }
        __syncthreads();
    }

    if (qq == 0) row_l[r] = l_run;
    __syncthreads();
    #pragma unroll
    for (int i = 0; i < 4; i++) {
        float inv = 1.0f / row_l[ty*4 + i];
        float4 o0 = make_float4(acc[i][0]*inv, acc[i][1]*inv, acc[i][2]*inv, acc[i][3]*inv);
        float4 o1 = make_float4(acc[i][4]*inv, acc[i][5]*inv, acc[i][6]*inv, acc[i][7]*inv);
        float* dst = g_attn + (size_t)(q0 + ty*4 + i) * (NH * HD) + h * HD + (tx << 3);
        *(float4*)(dst)     = o0;
        *(float4*)(dst + 4) = o1;
    }
}

// ---------------------------------------------------------------------------
extern "C" void kernel_launch(void* const* d_in, const int* in_sizes, int n_in,
                              void* d_out, int out_size) {
    const float* hidden = (const float*)d_in[0];
    const float* w_qkv  = (const float*)d_in[1];
    const float* w_o    = (const float*)d_in[2];
    float* out = (float*)d_out;

    float *qkv = nullptr, *attn = nullptr;
    cudaGetSymbolAddress((void**)&qkv,  g_qkv);
    cudaGetSymbolAddress((void**)&attn, g_attn);

    cudaFuncSetAttribute(tmma_gemm_nt, cudaFuncAttributeMaxDynamicSharedMemorySize,
                         GEMM_SMEM_TOTAL);
    cudaFuncSetAttribute(attn_kernel, cudaFuncAttributeMaxDynamicSharedMemorySize,
                         SM_TOTAL * (int)sizeof(float));

    // 1) QKV projection: [2048,6144] = hidden [2048,4096] @ w_qkv^T  (tf32 mma)
    tmma_gemm_nt<<<dim3(S_LEN / TBM, QKV_DIM / TBN), 256, GEMM_SMEM_TOTAL>>>(
        hidden, w_qkv, qkv, QKV_DIM, HIDDEN);

    // 2) RoPE on Q and K regions (40 heads x 64 pairs per token)
    rope_kernel<<<(S_LEN * 40 * 64 + 255) / 256, 256>>>();

    // 3) Causal GQA flash attention -> g_attn [2048, 4096]
    attn_kernel<<<dim3(S_LEN / ABM, NH), 256, SM_TOTAL * (int)sizeof(float)>>>();

    // 4) Output projection: out [2048,4096] = g_attn @ w_o^T  (tf32 mma)
    tmma_gemm_nt<<<dim3(S_LEN / TBM, HIDDEN / TBN), 256, GEMM_SMEM_TOTAL>>>(
        attn, w_o, out, HIDDEN, HIDDEN);
}

// round 5
// speedup vs baseline: 4.1651x; 1.7318x over previous
#include <cuda_runtime.h>
#include <cuda_bf16.h>
#include <cstdint>
#include <math.h>

#define S_LEN   2048
#define HIDDEN  4096
#define NH      32
#define NKVH    8
#define HD      128
#define QKV_DIM 6144      // (32 + 8 + 8) * 128
#define K_OFF   4096
#define V_OFF   5120

// Scratch (allocation-free rule: __device__ globals)
__device__ float g_qkv[S_LEN * QKV_DIM];            // ~50 MB
__device__ float g_attn[S_LEN * NH * HD];           // ~33 MB
__device__ __nv_bfloat16 g_qh[NH  * S_LEN * HD];    // 16 MB  [h][s][d]
__device__ __nv_bfloat16 g_ql[NH  * S_LEN * HD];
__device__ __nv_bfloat16 g_kh[NKVH * S_LEN * HD];   // 4 MB   [kvh][s][d]
__device__ __nv_bfloat16 g_kl[NKVH * S_LEN * HD];
__device__ __nv_bfloat16 g_vh[NKVH * S_LEN * HD];
__device__ __nv_bfloat16 g_vl[NKVH * S_LEN * HD];

__device__ __forceinline__ uint32_t smem_to_u32(const void* smem_ptr) {
    uint32_t addr;
    asm("{ .reg .u64 tmp; cvta.to.shared.u64 tmp, %1; cvt.u32.u64 %0, tmp; }"
        : "=r"(addr) : "l"(smem_ptr));
    return addr;
}

#define LDSM_X4(r0, r1, r2, r3, addr) \
    asm volatile("ldmatrix.sync.aligned.m8n8.x4.shared.b16 {%0,%1,%2,%3}, [%4];" \
                 : "=r"(r0), "=r"(r1), "=r"(r2), "=r"(r3) : "r"(addr))

#define LDSM_X4_T(r0, r1, r2, r3, addr) \
    asm volatile("ldmatrix.sync.aligned.m8n8.x4.trans.shared.b16 {%0,%1,%2,%3}, [%4];" \
                 : "=r"(r0), "=r"(r1), "=r"(r2), "=r"(r3) : "r"(addr))

#define CVT_TF32(x) \
    asm("cvt.rna.tf32.f32 %0, %1;" : "=r"(x) : "f"(__uint_as_float(x)))

#define MMA_TF32(d, a0, a1, a2, a3, b0, b1) \
    asm volatile("mma.sync.aligned.m16n8k8.row.col.f32.tf32.tf32.f32 " \
                 "{%0,%1,%2,%3}, {%4,%5,%6,%7}, {%8,%9}, {%0,%1,%2,%3};" \
                 : "+f"((d)[0]), "+f"((d)[1]), "+f"((d)[2]), "+f"((d)[3]) \
                 : "r"(a0), "r"(a1), "r"(a2), "r"(a3), "r"(b0), "r"(b1))

#define MMA_BF16(d, a, b0, b1) \
    asm volatile("mma.sync.aligned.m16n8k16.row.col.f32.bf16.bf16.f32 " \
                 "{%0,%1,%2,%3}, {%4,%5,%6,%7}, {%8,%9}, {%0,%1,%2,%3};" \
                 : "+f"((d)[0]), "+f"((d)[1]), "+f"((d)[2]), "+f"((d)[3]) \
                 : "r"((a)[0]), "r"((a)[1]), "r"((a)[2]), "r"((a)[3]), \
                   "r"(b0), "r"(b1))

#define CP_ASYNC16(dst, src) \
    asm volatile("cp.async.cg.shared.global [%0], [%1], 16;" \
                 :: "r"(dst), "l"(src) : "memory")
#define CP_COMMIT()  asm volatile("cp.async.commit_group;" ::: "memory")
#define CP_WAIT0()   asm volatile("cp.async.wait_group 0;" ::: "memory")
#define CP_WAIT1()   asm volatile("cp.async.wait_group 1;" ::: "memory")

__device__ __forceinline__ uint32_t pack_bf16_hi(float x, float y) {
    __nv_bfloat162 t = __floats2bfloat162_rn(x, y);
    return *reinterpret_cast<uint32_t*>(&t);
}
__device__ __forceinline__ uint32_t pack_bf16_lo(float x, float y, uint32_t hi) {
    __nv_bfloat162 h = *reinterpret_cast<__nv_bfloat162*>(&hi);
    __nv_bfloat162 t = __floats2bfloat162_rn(x - __bfloat162float(h.x),
                                             y - __bfloat162float(h.y));
    return *reinterpret_cast<uint32_t*>(&t);
}

// ===========================================================================
// tf32 mma.sync GEMM NT (unchanged from round 4 — passing at 224 TF/s)
// ===========================================================================
#define TBM 128
#define TBN 128
#define TBK 32
#define TILE_BYTES (TBM * TBK * 4)
#define BUF_STRIDE (2 * TILE_BYTES)
#define GEMM_SMEM_TOTAL (2 * BUF_STRIDE)

__global__ void __launch_bounds__(256) tmma_gemm_nt(const float* __restrict__ A,
                                                    const float* __restrict__ B,
                                                    float* __restrict__ C,
                                                    int N, int K) {
    extern __shared__ char smem[];
    const uint32_t sbase = smem_to_u32(smem);
    const int tid = threadIdx.x;
    const int lane = tid & 31;
    const int wid = tid >> 5;
    const int warp_m = wid & 1;
    const int warp_n = wid >> 1;
    const int row0 = blockIdx.x * TBM;
    const int col0 = blockIdx.y * TBN;

    const int seg = lane >> 3, r8 = lane & 7;
    const int a_row_off = ((seg & 1) << 3) + r8;
    const int a_kh = seg >> 1;
    const int b_row_off = ((seg >> 1) << 3) + r8;
    const int b_kh = seg & 1;

    float acc[4][4][4] = {};
    const int NCHUNK = K / TBK;

    auto load_chunk = [&](int c, int buf) {
        const uint32_t sA = sbase + (uint32_t)buf * BUF_STRIDE;
        const uint32_t sB = sA + TILE_BYTES;
        const int k0 = c * TBK;
        #pragma unroll
        for (int i = 0; i < 4; i++) {
            int e = tid + i * 256;
            int rr = e >> 3, cj = e & 7;
            uint32_t so = (uint32_t)rr * 128u + (uint32_t)((cj ^ (rr & 7)) << 4);
            const float* gA = A + (size_t)(row0 + rr) * K + k0 + cj * 4;
            const float* gB = B + (size_t)(col0 + rr) * K + k0 + cj * 4;
            CP_ASYNC16(sA + so, gA);
            CP_ASYNC16(sB + so, gB);
        }
        CP_COMMIT();
    };

    load_chunk(0, 0);
    for (int c = 0; c < NCHUNK; c++) {
        if (c + 1 < NCHUNK) {
            load_chunk(c + 1, (c + 1) & 1);
            CP_WAIT1();
        } else {
            CP_WAIT0();
        }
        __syncthreads();

        const uint32_t sA = sbase + (uint32_t)(c & 1) * BUF_STRIDE;
        const uint32_t sB = sA + TILE_BYTES;
        #pragma unroll
        for (int ks = 0; ks < 4; ks++) {
            uint32_t a[4][4], b[2][4];
            #pragma unroll
            for (int mf = 0; mf < 4; mf++) {
                int row = warp_m * 64 + mf * 16 + a_row_off;
                uint32_t g = (uint32_t)((ks * 2 + a_kh) ^ (row & 7));
                uint32_t addr = sA + (uint32_t)row * 128u + g * 16u;
                LDSM_X4(a[mf][0], a[mf][1], a[mf][2], a[mf][3], addr);
            }
            #pragma unroll
            for (int nf2 = 0; nf2 < 2; nf2++) {
                int row = warp_n * 32 + nf2 * 16 + b_row_off;
                uint32_t g = (uint32_t)((ks * 2 + b_kh) ^ (row & 7));
                uint32_t addr = sB + (uint32_t)row * 128u + g * 16u;
                LDSM_X4(b[nf2][0], b[nf2][1], b[nf2][2], b[nf2][3], addr);
            }
            #pragma unroll
            for (int mf = 0; mf < 4; mf++)
                #pragma unroll
                for (int i = 0; i < 4; i++) CVT_TF32(a[mf][i]);
            #pragma unroll
            for (int nf2 = 0; nf2 < 2; nf2++)
                #pragma unroll
                for (int i = 0; i < 4; i++) CVT_TF32(b[nf2][i]);
            #pragma unroll
            for (int mf = 0; mf < 4; mf++)
                #pragma unroll
                for (int nf = 0; nf < 4; nf++) {
                    uint32_t bb0 = b[nf >> 1][(nf & 1) * 2 + 0];
                    uint32_t bb1 = b[nf >> 1][(nf & 1) * 2 + 1];
                    MMA_TF32(acc[mf][nf], a[mf][0], a[mf][1], a[mf][2], a[mf][3],
                             bb0, bb1);
                }
        }
        __syncthreads();
    }

    #pragma unroll
    for (int mf = 0; mf < 4; mf++) {
        int grow = row0 + warp_m * 64 + mf * 16 + (lane >> 2);
        #pragma unroll
        for (int nf = 0; nf < 4; nf++) {
            int gcol = col0 + warp_n * 32 + nf * 8 + ((lane & 3) << 1);
            *(float2*)(C + (size_t)grow * N + gcol) =
                make_float2(acc[mf][nf][0], acc[mf][nf][1]);
            *(float2*)(C + (size_t)(grow + 8) * N + gcol) =
                make_float2(acc[mf][nf][2], acc[mf][nf][3]);
        }
    }
}

// ===========================================================================
// RoPE + bf16 hi/lo split pre-pass.
// One thread per (s, head 0..47, d-pair 0..63).
//  h<32 : Q head (RoPE + 1/sqrt(HD) scale) -> g_qh/g_ql [h][s][d]
//  h<40 : K head (RoPE)                    -> g_kh/g_kl [h-32][s][d]
//  else : V head (copy)                    -> g_vh/g_vl [h-40][s][d]
// ===========================================================================
__global__ void rope_split_kernel() {
    int idx = blockIdx.x * blockDim.x + threadIdx.x;
    if (idx >= S_LEN * 48 * 64) return;
    int d = idx & 63;
    int h = (idx >> 6) % 48;
    int s = idx / (64 * 48);

    float x1, x2;
    __nv_bfloat16 *dst_h, *dst_l;
    if (h < 32) {
        const float* src = g_qkv + (size_t)s * QKV_DIM + h * HD;
        x1 = src[d]; x2 = src[d + 64];
        dst_h = g_qh + ((size_t)h * S_LEN + s) * HD;
        dst_l = g_ql + ((size_t)h * S_LEN + s) * HD;
    } else if (h < 40) {
        const float* src = g_qkv + (size_t)s * QKV_DIM + K_OFF + (h - 32) * HD;
        x1 = src[d]; x2 = src[d + 64];
        dst_h = g_kh + ((size_t)(h - 32) * S_LEN + s) * HD;
        dst_l = g_kl + ((size_t)(h - 32) * S_LEN + s) * HD;
    } else {
        const float* src = g_qkv + (size_t)s * QKV_DIM + V_OFF + (h - 40) * HD;
        x1 = src[d]; x2 = src[d + 64];
        dst_h = g_vh + ((size_t)(h - 40) * S_LEN + s) * HD;
        dst_l = g_vl + ((size_t)(h - 40) * S_LEN + s) * HD;
    }

    float o1 = x1, o2 = x2;
    if (h < 40) {
        float freq = exp2f(-0.20762050593046013f * (float)d);
        float ang = (float)s * freq;
        float sn, cs;
        sincosf(ang, &sn, &cs);
        o1 = x1 * cs - x2 * sn;
        o2 = x1 * sn + x2 * cs;
    }
    if (h < 32) {
        const float scale = 0.08838834764831845f;   // 1/sqrt(128)
        o1 *= scale; o2 *= scale;
    }
    __nv_bfloat16 h1 = __float2bfloat16_rn(o1);
    __nv_bfloat16 h2 = __float2bfloat16_rn(o2);
    dst_h[d]      = h1;
    dst_h[d + 64] = h2;
    dst_l[d]      = __float2bfloat16_rn(o1 - __bfloat162float(h1));
    dst_l[d + 64] = __float2bfloat16_rn(o2 - __bfloat162float(h2));
}

// ===========================================================================
// Tensor-core flash attention, bf16 3-term compensated (hi*hi + hi*lo + lo*hi).
// CTA = 128 threads (4 warps), tile = 64 q x 64 k, warp owns 16 full rows.
// Smem: Qh Ql Kh Kl Vh Vl, each [64][128] bf16, 256B rows, XOR-8 swizzle.
// ===========================================================================
#define ATT_SMEM (6 * 64 * 128 * 2)    // 98304 bytes
#define SQH 0
#define SQL 16384
#define SKH 32768
#define SKL 49152
#define SVH 65536
#define SVL 81920

__global__ void __launch_bounds__(128, 2) attn_mma() {
    extern __shared__ char smem[];
    const uint32_t sb = smem_to_u32(smem);
    const int tid = threadIdx.x;
    const int lane = tid & 31;
    const int wid = tid >> 5;
    const int mb = 31 - (int)blockIdx.x;     // heaviest first
    const int h = blockIdx.y;
    const int kvh = h >> 2;
    const int q0 = mb * 64;
    const int wr = wid * 16;                 // warp row base within tile
    const int gr = lane >> 2, tg = lane & 3; // fragment row / col-pair roles
    const int seg = lane >> 3, r8 = lane & 7;

    const __nv_bfloat16* qh = g_qh + ((size_t)h * S_LEN + q0) * HD;
    const __nv_bfloat16* ql = g_ql + ((size_t)h * S_LEN + q0) * HD;
    const __nv_bfloat16* kh = g_kh + (size_t)kvh * S_LEN * HD;
    const __nv_bfloat16* kl = g_kl + (size_t)kvh * S_LEN * HD;
    const __nv_bfloat16* vh = g_vh + (size_t)kvh * S_LEN * HD;
    const __nv_bfloat16* vl = g_vl + (size_t)kvh * S_LEN * HD;

    // ---- async tile loaders: 64 rows x 256B, swizzled ----
    auto load_pair = [&](uint32_t dh, uint32_t dl,
                         const __nv_bfloat16* sh, const __nv_bfloat16* sl) {
        #pragma unroll
        for (int i = 0; i < 8; i++) {
            int e = tid + i * 128;           // 0..1023
            int r = e >> 4, g = e & 15;
            uint32_t so = (uint32_t)r * 256u + (uint32_t)((g ^ (r & 7)) << 4);
            CP_ASYNC16(dh + so, sh + (size_t)r * HD + g * 8);
            CP_ASYNC16(dl + so, sl + (size_t)r * HD + g * 8);
        }
    };

    load_pair(sb + SQH, sb + SQL, qh, ql);
    load_pair(sb + SKH, sb + SKL, kh, kl);
    load_pair(sb + SVH, sb + SVL, vh, vl);
    CP_COMMIT();
    CP_WAIT0();
    __syncthreads();

    float oacc[16][4] = {};
    const float NEG_INF = -__int_as_float(0x7f800000);
    float m0 = NEG_INF, m1 = NEG_INF, l0 = 0.0f, l1 = 0.0f;

    // precomputed ldsm lane-address pieces
    const int a_row = wr + ((seg & 1) << 3) + r8;        // Q rows (A frags)
    const int a_gsel = seg >> 1;                          // k granule +0/+1
    const int b_row_off = ((seg >> 1) << 3) + r8;         // K rows (B frags)
    const int b_gsel = seg & 1;
    const int v_row_off = ((seg & 1) << 3) + r8;          // V k-rows (trans)
    const int v_gsel = seg >> 1;

    for (int kb = 0; kb <= mb; kb++) {
        // ---------------- S = Q K^T (bf16 x3) ----------------
        float sacc[8][4] = {};
        #pragma unroll
        for (int kc = 0; kc < 8; kc++) {
            uint32_t qa_h[4], qa_l[4];
            {
                uint32_t g = (uint32_t)((2 * kc + a_gsel) ^ (a_row & 7));
                uint32_t off = (uint32_t)a_row * 256u + g * 16u;
                LDSM_X4(qa_h[0], qa_h[1], qa_h[2], qa_h[3], sb + SQH + off);
                LDSM_X4(qa_l[0], qa_l[1], qa_l[2], qa_l[3], sb + SQL + off);
            }
            #pragma unroll
            for (int nf2 = 0; nf2 < 4; nf2++) {
                int brow = nf2 * 16 + b_row_off;
                uint32_t g = (uint32_t)((2 * kc + b_gsel) ^ (brow & 7));
                uint32_t off = (uint32_t)brow * 256u + g * 16u;
                uint32_t bh0, bh1, bh2, bh3, bl0, bl1, bl2, bl3;
                LDSM_X4(bh0, bh1, bh2, bh3, sb + SKH + off);
                LDSM_X4(bl0, bl1, bl2, bl3, sb + SKL + off);
                MMA_BF16(sacc[2 * nf2],     qa_h, bh0, bh1);
                MMA_BF16(sacc[2 * nf2],     qa_l, bh0, bh1);
                MMA_BF16(sacc[2 * nf2],     qa_h, bl0, bl1);
                MMA_BF16(sacc[2 * nf2 + 1], qa_h, bh2, bh3);
                MMA_BF16(sacc[2 * nf2 + 1], qa_l, bh2, bh3);
                MMA_BF16(sacc[2 * nf2 + 1], qa_h, bl2, bl3);
            }
        }
        __syncthreads();                      // K tile consumed
        if (kb < mb)  {                       // prefetch next K (overlaps softmax+PV)
            load_pair(sb + SKH, sb + SKL,
                      kh + (size_t)(kb + 1) * 64 * HD,
                      kl + (size_t)(kb + 1) * 64 * HD);
            CP_COMMIT();
        }

        // ---------------- online softmax (registers only) ----------------
        const int row0g = q0 + wr + gr;
        const int row1g = row0g + 8;
        if (kb == mb) {
            const int n0 = kb * 64;
            #pragma unroll
            for (int nf = 0; nf < 8; nf++) {
                int c0 = n0 + nf * 8 + 2 * tg;
                if (c0 > row0g)     sacc[nf][0] = NEG_INF;
                if (c0 + 1 > row0g) sacc[nf][1] = NEG_INF;
                if (c0 > row1g)     sacc[nf][2] = NEG_INF;
                if (c0 + 1 > row1g) sacc[nf][3] = NEG_INF;
            }
        }
        float mx0 = NEG_INF, mx1 = NEG_INF;
        #pragma unroll
        for (int nf = 0; nf < 8; nf++) {
            mx0 = fmaxf(mx0, fmaxf(sacc[nf][0], sacc[nf][1]));
            mx1 = fmaxf(mx1, fmaxf(sacc[nf][2], sacc[nf][3]));
        }
        mx0 = fmaxf(mx0, __shfl_xor_sync(0xffffffffu, mx0, 1));
        mx0 = fmaxf(mx0, __shfl_xor_sync(0xffffffffu, mx0, 2));
        mx1 = fmaxf(mx1, __shfl_xor_sync(0xffffffffu, mx1, 1));
        mx1 = fmaxf(mx1, __shfl_xor_sync(0xffffffffu, mx1, 2));
        float mn0 = fmaxf(m0, mx0), mn1 = fmaxf(m1, mx1);
        float rs0 = __expf(m0 - mn0), rs1 = __expf(m1 - mn1);
        float sum0 = 0.0f, sum1 = 0.0f;
        #pragma unroll
        for (int nf = 0; nf < 8; nf++) {
            sacc[nf][0] = __expf(sacc[nf][0] - mn0); sum0 += sacc[nf][0];
            sacc[nf][1] = __expf(sacc[nf][1] - mn0); sum0 += sacc[nf][1];
            sacc[nf][2] = __expf(sacc[nf][2] - mn1); sum1 += sacc[nf][2];
            sacc[nf][3] = __expf(sacc[nf][3] - mn1); sum1 += sacc[nf][3];
        }
        sum0 += __shfl_xor_sync(0xffffffffu, sum0, 1);
        sum0 += __shfl_xor_sync(0xffffffffu, sum0, 2);
        sum1 += __shfl_xor_sync(0xffffffffu, sum1, 1);
        sum1 += __shfl_xor_sync(0xffffffffu, sum1, 2);
        l0 = l0 * rs0 + sum0; m0 = mn0;
        l1 = l1 * rs1 + sum1; m1 = mn1;
        #pragma unroll
        for (int nf = 0; nf < 16; nf++) {
            oacc[nf][0] *= rs0; oacc[nf][1] *= rs0;
            oacc[nf][2] *= rs1; oacc[nf][3] *= rs1;
        }

        // ---------------- O += P V (bf16 x3, P from regs) ----------------
        #pragma unroll
        for (int kc2 = 0; kc2 < 4; kc2++) {
            uint32_t pa_h[4], pa_l[4];
            pa_h[0] = pack_bf16_hi(sacc[2 * kc2][0],     sacc[2 * kc2][1]);
            pa_h[1] = pack_bf16_hi(sacc[2 * kc2][2],     sacc[2 * kc2][3]);
            pa_h[2] = pack_bf16_hi(sacc[2 * kc2 + 1][0], sacc[2 * kc2 + 1][1]);
            pa_h[3] = pack_bf16_hi(sacc[2 * kc2 + 1][2], sacc[2 * kc2 + 1][3]);
            pa_l[0] = pack_bf16_lo(sacc[2 * kc2][0],     sacc[2 * kc2][1],     pa_h[0]);
            pa_l[1] = pack_bf16_lo(sacc[2 * kc2][2],     sacc[2 * kc2][3],     pa_h[1]);
            pa_l[2] = pack_bf16_lo(sacc[2 * kc2 + 1][0], sacc[2 * kc2 + 1][1], pa_h[2]);
            pa_l[3] = pack_bf16_lo(sacc[2 * kc2 + 1][2], sacc[2 * kc2 + 1][3], pa_h[3]);
            int krow = 16 * kc2 + v_row_off;
            #pragma unroll
            for (int j = 0; j < 8; j++) {
                uint32_t g = (uint32_t)((2 * j + v_gsel) ^ (krow & 7));
                uint32_t off = (uint32_t)krow * 256u + g * 16u;
                uint32_t vh0, vh1, vh2, vh3, vl0, vl1, vl2, vl3;
                LDSM_X4_T(vh0, vh1, vh2, vh3, sb + SVH + off);
                LDSM_X4_T(vl0, vl1, vl2, vl3, sb + SVL + off);
                MMA_BF16(oacc[2 * j],     pa_h, vh0, vh1);
                MMA_BF16(oacc[2 * j],     pa_l, vh0, vh1);
                MMA_BF16(oacc[2 * j],     pa_h, vl0, vl1);
                MMA_BF16(oacc[2 * j + 1], pa_h, vh2, vh3);
                MMA_BF16(oacc[2 * j + 1], pa_l, vh2, vh3);
                MMA_BF16(oacc[2 * j + 1], pa_h, vl2, vl3);
            }
        }
        __syncthreads();                      // V tile consumed
        if (kb < mb) {
            load_pair(sb + SVH, sb + SVL,
                      vh + (size_t)(kb + 1) * 64 * HD,
                      vl + (size_t)(kb + 1) * 64 * HD);
            CP_COMMIT();
            CP_WAIT0();                       // K + V for next tile ready
            __syncthreads();
        }
    }

    // ---------------- normalize + writeout ----------------
    const float inv0 = 1.0f / l0, inv1 = 1.0f / l1;
    const int row0g = q0 + wr + gr;
    float* dst0 = g_attn + (size_t)row0g * (NH * HD) + h * HD;
    float* dst1 = dst0 + 8 * (size_t)(NH * HD);
    #pragma unroll
    for (int nf = 0; nf < 16; nf++) {
        int col = nf * 8 + 2 * tg;
        *(float2*)(dst0 + col) = make_float2(oacc[nf][0] * inv0, oacc[nf][1] * inv0);
        *(float2*)(dst1 + col) = make_float2(oacc[nf][2] * inv1, oacc[nf][3] * inv1);
    }
}

// ---------------------------------------------------------------------------
extern "C" void kernel_launch(void* const* d_in, const int* in_sizes, int n_in,
                              void* d_out, int out_size) {
    const float* hidden = (const float*)d_in[0];
    const float* w_qkv  = (const float*)d_in[1];
    const float* w_o    = (const float*)d_in[2];
    float* out = (float*)d_out;

    float *qkv = nullptr, *attn = nullptr;
    cudaGetSymbolAddress((void**)&qkv,  g_qkv);
    cudaGetSymbolAddress((void**)&attn, g_attn);

    cudaFuncSetAttribute(tmma_gemm_nt, cudaFuncAttributeMaxDynamicSharedMemorySize,
                         GEMM_SMEM_TOTAL);
    cudaFuncSetAttribute(attn_mma, cudaFuncAttributeMaxDynamicSharedMemorySize,
                         ATT_SMEM);

    // 1) QKV projection (tf32 mma): [2048,6144] = hidden @ w_qkv^T
    tmma_gemm_nt<<<dim3(S_LEN / TBM, QKV_DIM / TBN), 256, GEMM_SMEM_TOTAL>>>(
        hidden, w_qkv, qkv, QKV_DIM, HIDDEN);

    // 2) RoPE + scale + bf16 hi/lo split -> head-major Q/K/V
    rope_split_kernel<<<(S_LEN * 48 * 64 + 255) / 256, 256>>>();

    // 3) Causal GQA flash attention (bf16 x3 tensor core) -> g_attn
    attn_mma<<<dim3(32, NH), 128, ATT_SMEM>>>();

    // 4) Output projection (tf32 mma): out = g_attn @ w_o^T
    tmma_gemm_nt<<<dim3(S_LEN / TBM, HIDDEN / TBN), 256, GEMM_SMEM_TOTAL>>>(
        attn, w_o, out, HIDDEN, HIDDEN);
}